// round 17
// baseline (speedup 1.0000x reference)
#include <cuda_runtime.h>
#include <math.h>
#include <stdint.h>

// MultiLayerElmanRNN — round 13 (re-bench of R11 after infra failure).
// HMMA split-bf16 engine + producer-side split. Producers write each cell's
// activations to global scratch in the exact bf16 A-image the MMA consumes
// (64 hi rows; 64 lo rows; 1024B/row). Consumers stage with a pure
// cp.async.cg 128KB copy — no fp32 reload, no per-consumer split math.
// Wavefront skeleton and MMA fragment layout proven in R10.

#define SEQ    512
#define BATCH  64
#define HID    512
#define NL     4
#define SLICES 32
#define ROWS   16
#define NT     512

#define AST   1040            // smem A row stride (bytes): conflict-free ldmatrix
#define CELLB 131072          // scratch cell: 128 rows x 1024 B
// scratch slots per t: 0 = x-split, 1..4 = layer 0..3 output.
// Static __device__ scratch (sanctioned; no runtime allocation).
__device__ __align__(16) char g_scr[(size_t)SEQ * (NL + 1) * CELLB];
__device__ int g_cnt[NL * SEQ];

// SMEM layout (bytes)
#define A_O        0                       // A: 128 x AST = 133120
#define BIH_HI_O   133120                  // each W: 16 x AST = 16640
#define BIH_LO_O   149760
#define BHH_HI_O   166400
#define BHH_LO_O   183040
#define EXCH_O     199680                  // 16 tiles x 256 floats = 16384
#define BIAS_O     216064                  // 16 floats
#define SMEM_BYTES 216128

__global__ void reset_kernel() {
    int i = blockIdx.x * blockDim.x + threadIdx.x;
    if (i < NL * SEQ) g_cnt[i] = 0;
}

// fp32 pair -> bf16x2 hi / lo (lo = residual), lo-half = first element.
__device__ __forceinline__ void split2(float a, float b, uint32_t& hi, uint32_t& lo) {
    asm("cvt.rn.bf16x2.f32 %0, %1, %2;" : "=r"(hi) : "f"(b), "f"(a));
    float ha = __uint_as_float(hi << 16);
    float hb = __uint_as_float(hi & 0xFFFF0000u);
    asm("cvt.rn.bf16x2.f32 %0, %1, %2;" : "=r"(lo) : "f"(b - hb), "f"(a - ha));
}

__device__ __forceinline__ void split8_store(float4 v0, float4 v1, char* hi_p, char* lo_p) {
    uint4 H, L;
    split2(v0.x, v0.y, H.x, L.x);
    split2(v0.z, v0.w, H.y, L.y);
    split2(v1.x, v1.y, H.z, L.z);
    split2(v1.z, v1.w, H.w, L.w);
    *(uint4*)hi_p = H;
    *(uint4*)lo_p = L;
}

// Pre-split x into scratch slot 0 of every t (A-image layout).
__global__ void presplit_kernel(const float* __restrict__ x) {
    int idx = blockIdx.x * blockDim.x + threadIdx.x;   // SEQ*64*64 threads
    int t   = idx >> 12;
    int rem = idx & 4095;
    int b   = rem >> 6;
    int k0  = (rem & 63) << 3;
    const float* src = x + ((size_t)t * BATCH + b) * HID + k0;
    float4 v0 = *(const float4*)src;
    float4 v1 = *(const float4*)(src + 4);
    char* cell = g_scr + (size_t)t * (NL + 1) * CELLB;    // slot 0
    split8_store(v0, v1, cell + (size_t)b * 1024 + k0 * 2,
                         cell + (size_t)(b + 64) * 1024 + k0 * 2);
}

#define LDSM4(r0, r1, r2, r3, addr)                                         \
    asm volatile("ldmatrix.sync.aligned.m8n8.x4.shared.b16 {%0,%1,%2,%3}, [%4];" \
        : "=r"(r0), "=r"(r1), "=r"(r2), "=r"(r3) : "r"(addr))

#define MMA16816(c, a0, a1, a2, a3, b0, b1)                                 \
    asm volatile("mma.sync.aligned.m16n8k16.row.col.f32.bf16.bf16.f32 "      \
        "{%0,%1,%2,%3}, {%4,%5,%6,%7}, {%8,%9}, {%0,%1,%2,%3};"              \
        : "+f"((c)[0]), "+f"((c)[1]), "+f"((c)[2]), "+f"((c)[3])             \
        : "r"(a0), "r"(a1), "r"(a2), "r"(a3), "r"(b0), "r"(b1))

// One half (K=256 slice for this warp): 16 k-steps.
__device__ __forceinline__ void mma_pass(uint32_t aa, uint32_t bh, uint32_t bl,
                                         float* acc) {
#pragma unroll
    for (int kk = 0; kk < 16; kk++) {
        uint32_t a0, a1, a2, a3, h0, h1, h2, h3, l0, l1, l2, l3;
        LDSM4(a0, a1, a2, a3, aa);
        LDSM4(h0, h1, h2, h3, bh);
        LDSM4(l0, l1, l2, l3, bl);
        MMA16816(acc + 0,  a0, a1, a2, a3, h0, h1);
        MMA16816(acc + 4,  a0, a1, a2, a3, h2, h3);
        MMA16816(acc + 8,  a0, a1, a2, a3, l0, l1);
        MMA16816(acc + 12, a0, a1, a2, a3, l2, l3);
        aa += 32;
        bh += 32;
        bl += 32;
    }
}

// Stage one cell's A-image: 128KB gmem -> smem via cp.async.cg.
__device__ __forceinline__ void stage_async(const char* gbase, uint32_t sa_base, int tid) {
    int r = tid >> 2;
    int q = tid & 3;
    const char* g = gbase + (size_t)r * 1024 + q * 256;
    uint32_t sa = sa_base + (uint32_t)r * AST + q * 256;
#pragma unroll
    for (int i = 0; i < 16; i++) {
        asm volatile("cp.async.cg.shared.global [%0], [%1], 16;"
                     :: "r"(sa + i * 16), "l"(g + i * 16));
    }
    asm volatile("cp.async.commit_group;" ::: "memory");
}

__device__ __forceinline__ void cp_wait_all() {
    asm volatile("cp.async.wait_group 0;" ::: "memory");
}

__global__ __launch_bounds__(NT, 1)
void rnn_kernel(const float* __restrict__ x,
                const float* __restrict__ W_ih,
                const float* __restrict__ W_hh,
                const float* __restrict__ b_ih,
                const float* __restrict__ b_hh,
                float* __restrict__ out) {
    extern __shared__ char sm[];
    uint32_t sbase;
    asm("{ .reg .u64 t; cvta.to.shared.u64 t, %1; cvt.u32.u64 %0, t; }"
        : "=r"(sbase) : "l"(sm));

    const int l    = blockIdx.x / SLICES;
    const int s    = blockIdx.x % SLICES;
    const int tid  = threadIdx.x;
    const int wid  = tid >> 5;
    const int lane = tid & 31;
    const int row0 = s * ROWS;

    // ---- weights: split bf16 hi/lo, padded row-major (once) ----
    for (int idx = tid; idx < ROWS * 64; idx += NT) {
        int row = idx >> 6;
        int k0  = (idx & 63) << 3;
        const float* wih = W_ih + ((size_t)l * HID + row0 + row) * HID + k0;
        const float* whh = W_hh + ((size_t)l * HID + row0 + row) * HID + k0;
        float4 a0 = *(const float4*)wih;
        float4 a1 = *(const float4*)(wih + 4);
        split8_store(a0, a1, sm + BIH_HI_O + (size_t)row * AST + k0 * 2,
                             sm + BIH_LO_O + (size_t)row * AST + k0 * 2);
        float4 c0 = *(const float4*)whh;
        float4 c1 = *(const float4*)(whh + 4);
        split8_store(c0, c1, sm + BHH_HI_O + (size_t)row * AST + k0 * 2,
                             sm + BHH_LO_O + (size_t)row * AST + k0 * 2);
    }
    if (tid < ROWS) {
        ((float*)(sm + BIAS_O))[tid] = b_ih[l * HID + row0 + tid] + b_hh[l * HID + row0 + tid];
    }

    // ---- per-warp / per-lane fragment addresses (identical to R10) ----
    const int mt = wid & 7;
    const int kh = wid >> 3;
    const int tile = lane >> 3;
    const int tr   = lane & 7;
    const uint32_t a_lane = sbase + A_O
        + (uint32_t)(mt * 16 + ((tile & 1) << 3) + tr) * AST
        + (uint32_t)(kh * 512 + ((tile >> 1) << 4));
    const uint32_t b_off = (uint32_t)(((tile >> 1) << 3) + tr) * AST
        + (uint32_t)(kh * 512 + ((tile & 1) << 4));

    __syncthreads();

    volatile int* cnt = g_cnt;
    float* exf = (float*)(sm + EXCH_O);
    const float* bs = (const float*)(sm + BIAS_O);

    for (int t = 0; t < SEQ; t++) {
        float acc[16];
#pragma unroll
        for (int j = 0; j < 16; j++) acc[j] = 0.0f;

        // ===== recurrent half first (dep: (t-1, l), scratch slot l+1) =====
        if (t > 0) {
            if (tid == 0) {
                while (cnt[l * SEQ + (t - 1)] < SLICES) __nanosleep(20);
            }
            __syncthreads();
            __threadfence();
            stage_async(g_scr + ((size_t)(t - 1) * (NL + 1) + l + 1) * CELLB,
                        sbase + A_O, tid);
            cp_wait_all();
            __syncthreads();
            mma_pass(a_lane, sbase + BHH_HI_O + b_off, sbase + BHH_LO_O + b_off, acc);
        }

        // ===== input half (dep: (t, l-1), scratch slot l) =====
        if (l > 0) {
            if (tid == 0) {
                while (cnt[(l - 1) * SEQ + t] < SLICES) __nanosleep(20);
            }
        }
        __syncthreads();                 // A free after hh pass + wait published
        __threadfence();
        stage_async(g_scr + ((size_t)t * (NL + 1) + l) * CELLB, sbase + A_O, tid);
        cp_wait_all();
        __syncthreads();
        mma_pass(a_lane, sbase + BIH_HI_O + b_off, sbase + BIH_LO_O + b_off, acc);

        // ===== epilogue: exchange, fold, bias, tanh, store + scratch split =====
        {
            float s0[4], s1[4];
#pragma unroll
            for (int j = 0; j < 4; j++) {
                s0[j] = acc[j]     + acc[8 + j];
                s1[j] = acc[4 + j] + acc[12 + j];
            }
            float* base = exf + (size_t)(kh * 8 + mt) * 256;
            int g  = lane >> 2;
            int tq = lane & 3;
            *(float2*)(base + g * 16       + tq * 2)     = make_float2(s0[0], s0[1]);
            *(float2*)(base + (g + 8) * 16 + tq * 2)     = make_float2(s0[2], s0[3]);
            *(float2*)(base + g * 16       + 8 + tq * 2) = make_float2(s1[0], s1[1]);
            *(float2*)(base + (g + 8) * 16 + 8 + tq * 2) = make_float2(s1[2], s1[3]);
        }
        __syncthreads();
        {
            int b  = tid >> 3;
            int r  = (tid & 7) * 2;
            int t1 = b >> 4;
            int rw = (b & 15) * 16 + r;
            float2 vA = *(float2*)(exf + (size_t)t1 * 256 + rw);
            float2 vB = *(float2*)(exf + (size_t)(t1 + 4) * 256 + rw);
            float2 vC = *(float2*)(exf + (size_t)(t1 + 8) * 256 + rw);
            float2 vD = *(float2*)(exf + (size_t)(t1 + 12) * 256 + rw);
            float o0 = tanhf(vA.x + vB.x + vC.x + vD.x + bs[r]);
            float o1 = tanhf(vA.y + vB.y + vC.y + vD.y + bs[r + 1]);
            *(float2*)(out + ((size_t)(t * NL + l) * BATCH + b) * HID + row0 + r)
                = make_float2(o0, o1);
            // producer-side split into scratch slot l+1 (A-image layout)
            uint32_t hi, lo;
            split2(o0, o1, hi, lo);
            char* cell = g_scr + ((size_t)t * (NL + 1) + l + 1) * CELLB;
            *(uint32_t*)(cell + (size_t)b * 1024 + (row0 + r) * 2)        = hi;
            *(uint32_t*)(cell + (size_t)(b + 64) * 1024 + (row0 + r) * 2) = lo;
        }

        // ===== publish =====
        __threadfence();
        __syncthreads();
        if (tid == 0) atomicAdd(&g_cnt[l * SEQ + t], 1);
    }
}

extern "C" void kernel_launch(void* const* d_in, const int* in_sizes, int n_in,
                              void* d_out, int out_size) {
    const float* x    = (const float*)d_in[0];
    const float* W_ih = (const float*)d_in[1];
    const float* W_hh = (const float*)d_in[2];
    const float* b_ih = (const float*)d_in[3];
    const float* b_hh = (const float*)d_in[4];
    float* out = (float*)d_out;

    cudaFuncSetAttribute(rnn_kernel, cudaFuncAttributeMaxDynamicSharedMemorySize, SMEM_BYTES);

    reset_kernel<<<2, 1024>>>();
    presplit_kernel<<<SEQ * BATCH * 64 / 256, 256>>>(x);
    rnn_kernel<<<NL * SLICES, NT, SMEM_BYTES>>>(x, W_ih, W_hh, b_ih, b_hh, out);
}